// round 1
// baseline (speedup 1.0000x reference)
#include <cuda_runtime.h>
#include <math.h>

#define BATCH 32
#define NP 128   // predictions (columns after transpose)
#define NG 64    // ground truths (rows after transpose)

// per-sample partial results: coord + exist + count_sq
__device__ float g_partial[BATCH];

__global__ __launch_bounds__(128, 1)
void lsa_loss_kernel(const float* __restrict__ pred_coords, // [B,128,3]
                     const float* __restrict__ exist_probs, // [B,128]
                     const float* __restrict__ count_pred,  // [B,1]
                     const float* __restrict__ gt_coords,   // [B,64,3]
                     const int*   __restrict__ gt_counts,   // [B]
                     const float* __restrict__ weight)      // [1,128]
{
    // C[i*NP + j] = ||pred[j] - gt[i]||  (transposed cost, f32 like reference)
    __shared__ float  C[NG * NP];
    __shared__ float  gts[NG * 3];
    __shared__ double u[NG + 1];
    __shared__ double v[NP + 1];
    __shared__ double minv[NP + 1];
    __shared__ int    p[NP + 1];
    __shared__ int    way[NP + 1];
    __shared__ unsigned char used[NP + 1];
    __shared__ float  red[8];

    const int b   = blockIdx.x;
    const int tid = threadIdx.x;

    // ---- load GT coords to shared ----
    for (int idx = tid; idx < NG * 3; idx += 128)
        gts[idx] = gt_coords[b * NG * 3 + idx];
    __syncthreads();

    // ---- cost matrix: thread tid owns pred column tid ----
    const float px = pred_coords[(b * NP + tid) * 3 + 0];
    const float py = pred_coords[(b * NP + tid) * 3 + 1];
    const float pz = pred_coords[(b * NP + tid) * 3 + 2];
    #pragma unroll 4
    for (int i = 0; i < NG; i++) {
        float dx = px - gts[i * 3 + 0];
        float dy = py - gts[i * 3 + 1];
        float dz = pz - gts[i * 3 + 2];
        C[i * NP + tid] = sqrtf(dx * dx + dy * dy + dz * dz);
    }

    // ---- init duals / matching state ----
    for (int j = tid; j <= NP; j += 128) { v[j] = 0.0; p[j] = 0; way[j] = 0; }
    if (tid <= NG) u[tid] = 0.0;
    __syncthreads();

    // ---- Jonker–Volgenant, warp-synchronous on warp 0 ----
    // lane owns columns j = 1 + lane + 32k, k = 0..3
    if (tid < 32) {
        const int lane = tid;
        const double DINF = (double)INFINITY;

        for (int i = 1; i <= NG; i++) {
            if (lane == 0) { p[0] = i; used[0] = 0; }
            #pragma unroll
            for (int k = 0; k < 4; k++) {
                int j = 1 + lane + 32 * k;
                minv[j] = DINF;
                used[j] = 0;
            }
            __syncwarp();

            int j0 = 0;
            while (true) {
                // mark used[j0] (owner lane writes; owner is also the only reader)
                if (j0 == 0) { if (lane == 0) used[0] = 1; }
                else         { if (((j0 - 1) & 31) == lane) used[j0] = 1; }

                const int    i0  = p[j0];
                const double ui0 = u[i0];

                double bestval = DINF;
                int    bestidx = NP + 1;
                #pragma unroll
                for (int k = 0; k < 4; k++) {
                    int j = 1 + lane + 32 * k;
                    if (!used[j]) {
                        double cur = (double)C[(i0 - 1) * NP + (j - 1)] - ui0 - v[j];
                        if (cur < minv[j]) { minv[j] = cur; way[j] = j0; }
                        double mv = minv[j];
                        if (mv < bestval || (mv == bestval && j < bestidx)) {
                            bestval = mv; bestidx = j;
                        }
                    }
                }
                // butterfly argmin (tie -> lowest column index, matches np.argmin)
                #pragma unroll
                for (int off = 16; off; off >>= 1) {
                    double oval = __shfl_xor_sync(0xffffffffu, bestval, off);
                    int    oidx = __shfl_xor_sync(0xffffffffu, bestidx, off);
                    if (oval < bestval || (oval == bestval && oidx < bestidx)) {
                        bestval = oval; bestidx = oidx;
                    }
                }
                const int    j1    = bestidx;
                const double delta = bestval;

                // dual updates
                #pragma unroll
                for (int k = 0; k < 4; k++) {
                    int j = 1 + lane + 32 * k;
                    if (used[j]) { u[p[j]] += delta; v[j] -= delta; }
                    else          minv[j] -= delta;
                }
                if (lane == 0) { u[p[0]] += delta; v[0] -= delta; } // col 0 always used here
                __syncwarp();

                j0 = j1;
                if (p[j0] == 0) break;
            }
            // augment along alternating path
            if (lane == 0) {
                int jj = j0;
                while (jj) { int jprev = way[jj]; p[jj] = p[jprev]; jj = jprev; }
            }
            __syncwarp();
        }
    }
    __syncthreads();

    // ---- loss epilogue: thread tid = pred index tid, 1-based col j = tid+1 ----
    const int   gi = p[tid + 1];            // 1-based gt row, 0 if unmatched
    const float w  = weight[tid];
    const float pr = exist_probs[b * NP + tid];
    const float lp    = fmaxf(logf(pr),    -100.0f);
    const float l1mp  = fmaxf(log1pf(-pr), -100.0f);

    float bce;
    float sl1 = 0.0f;
    if (gi) {
        bce = -lp * w;
        float d0 = fabsf(px - gts[(gi - 1) * 3 + 0]);
        float d1 = fabsf(py - gts[(gi - 1) * 3 + 1]);
        float d2 = fabsf(pz - gts[(gi - 1) * 3 + 2]);
        sl1 += (d0 < 1.0f) ? 0.5f * d0 * d0 : d0 - 0.5f;
        sl1 += (d1 < 1.0f) ? 0.5f * d1 * d1 : d1 - 0.5f;
        sl1 += (d2 < 1.0f) ? 0.5f * d2 * d2 : d2 - 0.5f;
    } else {
        bce = -l1mp * w;
    }

    // block reduce (sl1 sum, bce sum)
    float s1 = sl1, s2 = bce;
    #pragma unroll
    for (int off = 16; off; off >>= 1) {
        s1 += __shfl_xor_sync(0xffffffffu, s1, off);
        s2 += __shfl_xor_sync(0xffffffffu, s2, off);
    }
    const int wid = tid >> 5;
    if ((tid & 31) == 0) { red[wid] = s1; red[4 + wid] = s2; }
    __syncthreads();
    if (tid == 0) {
        float coord = (red[0] + red[1] + red[2] + red[3]) / (float)(NG * 3);
        float exist = (red[4] + red[5] + red[6] + red[7]) / (float)NP;
        float cd = count_pred[b] - (float)gt_counts[b];
        g_partial[b] = coord + exist + cd * cd;
    }
}

__global__ void finalize_kernel(float* __restrict__ out)
{
    if (threadIdx.x == 0) {
        float s = 0.0f;
        #pragma unroll
        for (int b = 0; b < BATCH; b++) s += g_partial[b];
        out[0] = s / (float)BATCH;
    }
}

extern "C" void kernel_launch(void* const* d_in, const int* in_sizes, int n_in,
                              void* d_out, int out_size)
{
    const float* pred_coords = (const float*)d_in[0]; // [32,128,3]
    const float* exist_probs = (const float*)d_in[1]; // [32,128]
    const float* count_pred  = (const float*)d_in[2]; // [32,1]
    const float* gt_coords   = (const float*)d_in[3]; // [32,64,3]
    const int*   gt_counts   = (const int*)  d_in[4]; // [32]
    const float* weight      = (const float*)d_in[5]; // [1,128]
    float* out = (float*)d_out;

    lsa_loss_kernel<<<BATCH, 128>>>(pred_coords, exist_probs, count_pred,
                                    gt_coords, gt_counts, weight);
    finalize_kernel<<<1, 32>>>(out);
}

// round 2
// speedup vs baseline: 6.0461x; 6.0461x over previous
#include <cuda_runtime.h>
#include <math.h>

#define BATCH 32
#define NP 128   // predictions (columns)
#define NG 64    // ground truths (rows)

__device__ float g_partial[BATCH];
__device__ int   g_ready;        // zero-init; self-restoring

// order-preserving float32 <-> uint32 map (monotone: a<b  <=>  f2ord(a)<f2ord(b))
__device__ __forceinline__ unsigned f2ord(float f) {
    unsigned b = __float_as_uint(f);
    return b ^ ((b & 0x80000000u) ? 0xFFFFFFFFu : 0x80000000u);
}
__device__ __forceinline__ float ord2f(unsigned k) {
    unsigned b = k ^ ((k & 0x80000000u) ? 0x80000000u : 0xFFFFFFFFu);
    return __uint_as_float(b);
}

__global__ __launch_bounds__(128, 1)
void lsa_loss_kernel(const float* __restrict__ pred_coords, // [B,128,3]
                     const float* __restrict__ exist_probs, // [B,128]
                     const float* __restrict__ count_pred,  // [B,1]
                     const float* __restrict__ gt_coords,   // [B,64,3]
                     const int*   __restrict__ gt_counts,   // [B]
                     const float* __restrict__ weight,      // [1,128]
                     float*       __restrict__ out)
{
    __shared__ float C[NG * NP];      // C[i][j] = ||pred_j - gt_i||, f32
    __shared__ float gts[NG * 3];
    __shared__ float u_sh[NG];        // row duals
    __shared__ int   p_sh[NP];        // matched row per column, -1 = unmatched
    __shared__ int   way_sh[NP];      // predecessor column on shortest path
    __shared__ float red[8];

    const int b   = blockIdx.x;
    const int tid = threadIdx.x;

    // ---- load GT coords, init state ----
    for (int idx = tid; idx < NG * 3; idx += 128)
        gts[idx] = gt_coords[b * NG * 3 + idx];
    if (tid < NG) u_sh[tid] = 0.0f;
    p_sh[tid] = -1;
    __syncthreads();

    // ---- cost matrix: thread tid owns pred column tid ----
    const float px = pred_coords[(b * NP + tid) * 3 + 0];
    const float py = pred_coords[(b * NP + tid) * 3 + 1];
    const float pz = pred_coords[(b * NP + tid) * 3 + 2];
    #pragma unroll 4
    for (int i = 0; i < NG; i++) {
        float dx = px - gts[i * 3 + 0];
        float dy = py - gts[i * 3 + 1];
        float dz = pz - gts[i * 3 + 2];
        C[i * NP + tid] = sqrtf(dx * dx + dy * dy + dz * dz);
    }
    __syncthreads();

    // ---- Jonker–Volgenant (deferred duals / Dijkstra form), warp 0 ----
    // Lane owns columns j = 4*lane + k, k = 0..3.  dist/v/used in registers.
    if (tid < 32) {
        const int lane = tid;
        float v[4] = {0.0f, 0.0f, 0.0f, 0.0f};

        for (int i = 0; i < NG; i++) {
            float dist[4] = {__int_as_float(0x7F800000), __int_as_float(0x7F800000),
                             __int_as_float(0x7F800000), __int_as_float(0x7F800000)};
            unsigned usedm = 0;
            int   i0    = i;       // row being expanded (source = new row i)
            int   jprev = -1;      // -1 = virtual source
            float dist0 = 0.0f;    // shortest dist to jprev
            int   j1;
            float distF;

            while (true) {
                const float u0 = u_sh[i0];
                const float4 c4 = *(const float4*)&C[i0 * NP + 4 * lane];
                const float cc[4] = {c4.x, c4.y, c4.z, c4.w};
                const float s = dist0 - u0;

                unsigned lkey = 0xFFFFFFFFu;
                #pragma unroll
                for (int k = 0; k < 4; k++) {
                    if (!((usedm >> k) & 1u)) {
                        float cur = s + (cc[k] - v[k]);
                        if (cur < dist[k]) { dist[k] = cur; way_sh[4 * lane + k] = jprev; }
                        unsigned key = f2ord(dist[k]);
                        lkey = lkey < key ? lkey : key;
                    }
                }
                // exact f32 argmin with lowest-column tiebreak (matches np.argmin)
                const unsigned kmin = __reduce_min_sync(0xFFFFFFFFu, lkey);
                unsigned lj = 0xFFFFFFFFu;
                #pragma unroll
                for (int k = 0; k < 4; k++) {
                    if (!((usedm >> k) & 1u) && f2ord(dist[k]) == kmin) {
                        unsigned j = (unsigned)(4 * lane + k);
                        lj = lj < j ? lj : j;
                    }
                }
                j1    = (int)__reduce_min_sync(0xFFFFFFFFu, lj);
                distF = ord2f(kmin);

                const int pj = p_sh[j1];
                if (pj < 0) break;                       // found free column
                if ((j1 >> 2) == lane) usedm |= 1u << (j1 & 3);
                jprev = j1; dist0 = distF; i0 = pj;
            }

            // ---- dual updates (before augmentation; uses pre-augment p) ----
            #pragma unroll
            for (int k = 0; k < 4; k++) {
                if ((usedm >> k) & 1u) {
                    float d = distF - dist[k];
                    v[k] -= d;
                    int r = p_sh[4 * lane + k];
                    u_sh[r] += d;                        // rows on path are distinct
                }
            }
            if (lane == 0) u_sh[i] += distF;
            __syncwarp();

            // ---- augment along predecessor chain ----
            if (lane == 0) {
                int j = j1;
                while (true) {
                    int r = way_sh[j];
                    p_sh[j] = (r < 0) ? i : p_sh[r];
                    if (r < 0) break;
                    j = r;
                }
            }
            __syncwarp();
        }
    }
    __syncthreads();

    // ---- loss epilogue: thread tid = pred column tid ----
    const int   gi = p_sh[tid];              // matched gt row, -1 if unmatched
    const float w  = weight[tid];
    const float pr = exist_probs[b * NP + tid];

    float bce;
    float sl1 = 0.0f;
    if (gi >= 0) {
        bce = -fmaxf(logf(pr), -100.0f) * w;
        float d0 = fabsf(px - gts[gi * 3 + 0]);
        float d1 = fabsf(py - gts[gi * 3 + 1]);
        float d2 = fabsf(pz - gts[gi * 3 + 2]);
        sl1 += (d0 < 1.0f) ? 0.5f * d0 * d0 : d0 - 0.5f;
        sl1 += (d1 < 1.0f) ? 0.5f * d1 * d1 : d1 - 0.5f;
        sl1 += (d2 < 1.0f) ? 0.5f * d2 * d2 : d2 - 0.5f;
    } else {
        bce = -fmaxf(log1pf(-pr), -100.0f) * w;
    }

    // ---- block reduce (sl1, bce) ----
    float s1 = sl1, s2 = bce;
    #pragma unroll
    for (int off = 16; off; off >>= 1) {
        s1 += __shfl_xor_sync(0xffffffffu, s1, off);
        s2 += __shfl_xor_sync(0xffffffffu, s2, off);
    }
    const int wid = tid >> 5;
    if ((tid & 31) == 0) { red[wid] = s1; red[4 + wid] = s2; }
    __syncthreads();

    if (tid == 0) {
        float coord = (red[0] + red[1] + red[2] + red[3]) * (1.0f / (NG * 3));
        float exist = (red[4] + red[5] + red[6] + red[7]) * (1.0f / NP);
        float cd = count_pred[b] - (float)gt_counts[b];
        g_partial[b] = coord + exist + cd * cd;
        __threadfence();
        int old = atomicAdd(&g_ready, 1);
        if (old == BATCH - 1) {                 // last block finalizes
            __threadfence();
            float s = 0.0f;
            #pragma unroll
            for (int bb = 0; bb < BATCH; bb++)
                s += ((volatile float*)g_partial)[bb];
            out[0] = s * (1.0f / BATCH);
            g_ready = 0;                        // restore for next replay
        }
    }
}

extern "C" void kernel_launch(void* const* d_in, const int* in_sizes, int n_in,
                              void* d_out, int out_size)
{
    const float* pred_coords = (const float*)d_in[0]; // [32,128,3]
    const float* exist_probs = (const float*)d_in[1]; // [32,128]
    const float* count_pred  = (const float*)d_in[2]; // [32,1]
    const float* gt_coords   = (const float*)d_in[3]; // [32,64,3]
    const int*   gt_counts   = (const int*)  d_in[4]; // [32]
    const float* weight      = (const float*)d_in[5]; // [1,128]
    float* out = (float*)d_out;

    lsa_loss_kernel<<<BATCH, 128>>>(pred_coords, exist_probs, count_pred,
                                    gt_coords, gt_counts, weight, out);
}

// round 6
// speedup vs baseline: 9.3503x; 1.5465x over previous
#include <cuda_runtime.h>
#include <math.h>

#define BATCH 32
#define NP 128   // predictions (columns)
#define NG 64    // ground truths (rows)

__device__ float g_partial[BATCH];
__device__ int   g_ready;        // zero-init; self-restoring

// order-preserving float32 <-> uint32 map
__device__ __forceinline__ unsigned f2ord(float f) {
    unsigned b = __float_as_uint(f);
    return b ^ ((b & 0x80000000u) ? 0xFFFFFFFFu : 0x80000000u);
}
__device__ __forceinline__ float ord2f(unsigned k) {
    unsigned b = k ^ ((k & 0x80000000u) ? 0x80000000u : 0xFFFFFFFFu);
    return __uint_as_float(b);
}

__global__ __launch_bounds__(128, 1)
void lsa_loss_kernel(const float* __restrict__ pred_coords, // [B,128,3]
                     const float* __restrict__ exist_probs, // [B,128]
                     const float* __restrict__ count_pred,  // [B,1]
                     const float* __restrict__ gt_coords,   // [B,64,3]
                     const int*   __restrict__ gt_counts,   // [B]
                     const float* __restrict__ weight,      // [1,128]
                     float*       __restrict__ out)
{
    __shared__ float C[NG * NP];      // C[i][j] = ||pred_j - gt_i||, f32
    __shared__ float gts[NG * 3];
    __shared__ float u_sh[NG];        // row duals
    __shared__ int   p_sh[NP];        // matched row per column, -1 = unmatched
    __shared__ int   way_sh[NP];      // predecessor column on shortest path
    __shared__ int   claim[NP];       // greedy conflict resolution
    __shared__ int   row_free[NG];    // 1 = row needs augmentation
    __shared__ float red[8];

    const int b   = blockIdx.x;
    const int tid = threadIdx.x;

    // ---- load GT coords, init state ----
    for (int idx = tid; idx < NG * 3; idx += 128)
        gts[idx] = gt_coords[b * NG * 3 + idx];
    p_sh[tid]  = -1;
    claim[tid] = 0x7FFFFFFF;
    __syncthreads();

    // ---- cost matrix: thread tid owns pred column tid ----
    const float px = pred_coords[(b * NP + tid) * 3 + 0];
    const float py = pred_coords[(b * NP + tid) * 3 + 1];
    const float pz = pred_coords[(b * NP + tid) * 3 + 2];
    #pragma unroll 4
    for (int i = 0; i < NG; i++) {
        float dx = px - gts[i * 3 + 0];
        float dy = py - gts[i * 3 + 1];
        float dz = pz - gts[i * 3 + 2];
        C[i * NP + tid] = sqrtf(dx * dx + dy * dy + dz * dz);
    }
    __syncthreads();

    // ---- JV warm start: row reduction + greedy assignment ----
    // Thread i (< NG) scans row i: u[i] = min_j C[i][j]; claim argmin column.
    int my_arg = -1;
    if (tid < NG) {
        // two independent half-row chains for ILP, merge prefers lower index
        float b0 = __int_as_float(0x7F800000); int j0i = 0;
        float b1 = __int_as_float(0x7F800000); int j1i = 64;
        const float* row = &C[tid * NP];
        #pragma unroll 16
        for (int j = 0; j < 64; j++) {
            float c0 = row[j];
            float c1 = row[j + 64];
            if (c0 < b0) { b0 = c0; j0i = j; }
            if (c1 < b1) { b1 = c1; j1i = j + 64; }
        }
        float bm; int jm;
        if (b1 < b0) { bm = b1; jm = j1i; } else { bm = b0; jm = j0i; }
        u_sh[tid] = bm;
        my_arg = jm;
        atomicMin(&claim[jm], tid);      // earliest row wins (greedy order)
    }
    __syncthreads();
    if (tid < NG) {
        if (claim[my_arg] == tid) { p_sh[my_arg] = tid; row_free[tid] = 0; }
        else                      { row_free[tid] = 1; }
    }
    __syncthreads();

    // ---- JV augmentation for remaining rows (deferred duals), warp 0 ----
    // Lane owns columns j = 4*lane + k.  dist/v/used in registers.
    if (tid < 32) {
        const int lane = tid;
        float v[4] = {0.0f, 0.0f, 0.0f, 0.0f};

        for (int i = 0; i < NG; i++) {
            if (!row_free[i]) continue;

            float dist[4] = {__int_as_float(0x7F800000), __int_as_float(0x7F800000),
                             __int_as_float(0x7F800000), __int_as_float(0x7F800000)};
            unsigned usedm = 0;
            int   i0    = i;
            int   jprev = -1;      // -1 = virtual source
            float dist0 = 0.0f;
            int   j1;
            float distF;

            while (true) {
                const float u0 = u_sh[i0];
                const float4 c4 = *(const float4*)&C[i0 * NP + 4 * lane];
                const float cc[4] = {c4.x, c4.y, c4.z, c4.w};
                const float s = dist0 - u0;

                unsigned lkey = 0xFFFFFFFFu;
                #pragma unroll
                for (int k = 0; k < 4; k++) {
                    if (!((usedm >> k) & 1u)) {
                        float cur = s + (cc[k] - v[k]);
                        if (cur < dist[k]) { dist[k] = cur; way_sh[4 * lane + k] = jprev; }
                        unsigned key = f2ord(dist[k]);
                        lkey = lkey < key ? lkey : key;
                    }
                }
                const unsigned kmin = __reduce_min_sync(0xFFFFFFFFu, lkey);
                unsigned lj = 0xFFFFFFFFu;
                #pragma unroll
                for (int k = 0; k < 4; k++) {
                    if (!((usedm >> k) & 1u) && f2ord(dist[k]) == kmin) {
                        unsigned j = (unsigned)(4 * lane + k);
                        lj = lj < j ? lj : j;
                    }
                }
                j1    = (int)__reduce_min_sync(0xFFFFFFFFu, lj);
                distF = ord2f(kmin);

                const int pj = p_sh[j1];
                if (pj < 0) break;                       // free column found
                if ((j1 >> 2) == lane) usedm |= 1u << (j1 & 3);
                jprev = j1; dist0 = distF; i0 = pj;
            }

            // ---- dual updates (pre-augmentation p) ----
            #pragma unroll
            for (int k = 0; k < 4; k++) {
                if ((usedm >> k) & 1u) {
                    float d = distF - dist[k];
                    v[k] -= d;
                    int r = p_sh[4 * lane + k];
                    u_sh[r] += d;
                }
            }
            if (lane == 0) u_sh[i] += distF;
            __syncwarp();

            // ---- augment along predecessor chain ----
            if (lane == 0) {
                int j = j1;
                while (true) {
                    int r = way_sh[j];
                    p_sh[j] = (r < 0) ? i : p_sh[r];
                    if (r < 0) break;
                    j = r;
                }
            }
            __syncwarp();
        }
    }
    __syncthreads();

    // ---- loss epilogue: thread tid = pred column tid ----
    const int   gi = p_sh[tid];              // matched gt row, -1 if unmatched
    const float w  = weight[tid];
    const float pr = exist_probs[b * NP + tid];

    float bce;
    float sl1 = 0.0f;
    if (gi >= 0) {
        bce = -fmaxf(logf(pr), -100.0f) * w;
        float d0 = fabsf(px - gts[gi * 3 + 0]);
        float d1 = fabsf(py - gts[gi * 3 + 1]);
        float d2 = fabsf(pz - gts[gi * 3 + 2]);
        sl1 += (d0 < 1.0f) ? 0.5f * d0 * d0 : d0 - 0.5f;
        sl1 += (d1 < 1.0f) ? 0.5f * d1 * d1 : d1 - 0.5f;
        sl1 += (d2 < 1.0f) ? 0.5f * d2 * d2 : d2 - 0.5f;
    } else {
        bce = -fmaxf(log1pf(-pr), -100.0f) * w;
    }

    // ---- block reduce (sl1, bce) ----
    float s1 = sl1, s2 = bce;
    #pragma unroll
    for (int off = 16; off; off >>= 1) {
        s1 += __shfl_xor_sync(0xffffffffu, s1, off);
        s2 += __shfl_xor_sync(0xffffffffu, s2, off);
    }
    const int wid = tid >> 5;
    if ((tid & 31) == 0) { red[wid] = s1; red[4 + wid] = s2; }
    __syncthreads();

    if (tid == 0) {
        float coord = (red[0] + red[1] + red[2] + red[3]) * (1.0f / (NG * 3));
        float exist = (red[4] + red[5] + red[6] + red[7]) * (1.0f / NP);
        float cd = count_pred[b] - (float)gt_counts[b];
        g_partial[b] = coord + exist + cd * cd;
        __threadfence();
        int old = atomicAdd(&g_ready, 1);
        if (old == BATCH - 1) {                 // last block finalizes
            __threadfence();
            float s = 0.0f;
            #pragma unroll
            for (int bb = 0; bb < BATCH; bb++)
                s += ((volatile float*)g_partial)[bb];
            out[0] = s * (1.0f / BATCH);
            g_ready = 0;                        // restore for next replay
        }
    }
}

extern "C" void kernel_launch(void* const* d_in, const int* in_sizes, int n_in,
                              void* d_out, int out_size)
{
    const float* pred_coords = (const float*)d_in[0]; // [32,128,3]
    const float* exist_probs = (const float*)d_in[1]; // [32,128]
    const float* count_pred  = (const float*)d_in[2]; // [32,1]
    const float* gt_coords   = (const float*)d_in[3]; // [32,64,3]
    const int*   gt_counts   = (const int*)  d_in[4]; // [32]
    const float* weight      = (const float*)d_in[5]; // [1,128]
    float* out = (float*)d_out;

    lsa_loss_kernel<<<BATCH, 128>>>(pred_coords, exist_probs, count_pred,
                                    gt_coords, gt_counts, weight, out);
}

// round 7
// speedup vs baseline: 11.5910x; 1.2396x over previous
#include <cuda_runtime.h>
#include <math.h>

#define BATCH 32
#define NP 128   // predictions (columns)
#define NG 64    // ground truths (rows)
#define FULLMASK 0xFFFFFFFFu

__device__ float g_partial[BATCH];
__device__ int   g_ready;        // zero-init; self-restoring

// order-preserving float32 <-> uint32 map
__device__ __forceinline__ unsigned f2ord(float f) {
    unsigned b = __float_as_uint(f);
    return b ^ ((b & 0x80000000u) ? 0xFFFFFFFFu : 0x80000000u);
}
__device__ __forceinline__ float ord2f(unsigned k) {
    unsigned b = k ^ ((k & 0x80000000u) ? 0x80000000u : 0xFFFFFFFFu);
    return __uint_as_float(b);
}

__global__ __launch_bounds__(128, 1)
void lsa_loss_kernel(const float* __restrict__ pred_coords, // [B,128,3]
                     const float* __restrict__ exist_probs, // [B,128]
                     const float* __restrict__ count_pred,  // [B,1]
                     const float* __restrict__ gt_coords,   // [B,64,3]
                     const int*   __restrict__ gt_counts,   // [B]
                     const float* __restrict__ weight,      // [1,128]
                     float*       __restrict__ out)
{
    __shared__ float C[NG * NP];      // C[i][j] = ||pred_j - gt_i||, f32
    __shared__ float gts[NG * 3];
    __shared__ float u_sh[NG];        // row duals
    __shared__ float v_sh[NP];        // column duals
    __shared__ int   p_sh[NP];        // matched row per column, -1 = unmatched
    __shared__ int   way_sh[NP];      // predecessor column on shortest path
    __shared__ int   claim[NP];       // greedy conflict resolution
    __shared__ int   row_free[NG];
    __shared__ int   freeq[NG + 160]; // free-row queue (initial + ARR appends)
    __shared__ float red[8];

    const int b   = blockIdx.x;
    const int tid = threadIdx.x;

    // ---- load GT coords, init state ----
    for (int idx = tid; idx < NG * 3; idx += 128)
        gts[idx] = gt_coords[b * NG * 3 + idx];
    p_sh[tid]  = -1;
    claim[tid] = 0x7FFFFFFF;
    v_sh[tid]  = 0.0f;
    __syncthreads();

    // ---- cost matrix: thread tid owns pred column tid ----
    const float px = pred_coords[(b * NP + tid) * 3 + 0];
    const float py = pred_coords[(b * NP + tid) * 3 + 1];
    const float pz = pred_coords[(b * NP + tid) * 3 + 2];
    #pragma unroll 4
    for (int i = 0; i < NG; i++) {
        float dx = px - gts[i * 3 + 0];
        float dy = py - gts[i * 3 + 1];
        float dz = pz - gts[i * 3 + 2];
        C[i * NP + tid] = sqrtf(dx * dx + dy * dy + dz * dz);
    }
    __syncthreads();

    // ---- row reduction + greedy assignment ----
    int my_arg = -1;
    if (tid < NG) {
        float b0 = __int_as_float(0x7F800000); int j0i = 0;
        float b1 = __int_as_float(0x7F800000); int j1i = 64;
        const float* row = &C[tid * NP];
        #pragma unroll 16
        for (int j = 0; j < 64; j++) {
            float c0 = row[j];
            float c1 = row[j + 64];
            if (c0 < b0) { b0 = c0; j0i = j; }
            if (c1 < b1) { b1 = c1; j1i = j + 64; }
        }
        float bm; int jm;
        if (b1 < b0) { bm = b1; jm = j1i; } else { bm = b0; jm = j0i; }
        u_sh[tid] = bm;
        my_arg = jm;
        atomicMin(&claim[jm], tid);
    }
    __syncthreads();
    if (tid < NG) {
        if (claim[my_arg] == tid) { p_sh[my_arg] = tid; row_free[tid] = 0; }
        else                      { row_free[tid] = 1; }
    }
    __syncthreads();

    // ================= warp 0: ARR + Dijkstra augmentation =================
    if (tid < 32) {
        const int lane = tid;

        // ---- build free-row queue (ascending row order) ----
        unsigned fm0 = __ballot_sync(FULLMASK, row_free[lane]      != 0);
        unsigned fm1 = __ballot_sync(FULLMASK, row_free[32 + lane] != 0);
        int n0 = __popc(fm0);
        int nfree = n0 + __popc(fm1);
        if (fm0 & (1u << lane)) freeq[__popc(fm0 & ((1u << lane) - 1))] = lane;
        if (fm1 & (1u << lane)) freeq[n0 + __popc(fm1 & ((1u << lane) - 1))] = 32 + lane;
        __syncwarp();

        // ---- Augmenting Row Reduction (bounded) ----
        // All lanes perform scalar updates redundantly (same value, same addr)
        // so no __syncwarp is needed inside the loop.
        int head = 0, tail = nfree;
        int budget = 2 * nfree + 16;
        while (head < tail && budget > 0) {
            budget--;
            const int i = freeq[head++];

            const float4 c4 = *(const float4*)&C[i * NP + 4 * lane];
            const float4 v4 = *(const float4*)&v_sh[4 * lane];
            unsigned k0 = f2ord(c4.x - v4.x);
            unsigned k1 = f2ord(c4.y - v4.y);
            unsigned k2 = f2ord(c4.z - v4.z);
            unsigned k3 = f2ord(c4.w - v4.w);
            unsigned m1 = k0, m2 = 0xFFFFFFFFu; int jl = 0;
            if (k1 < m1) { m2 = m1; m1 = k1; jl = 1; } else m2 = k1;
            if (k2 < m1) { m2 = m1; m1 = k2; jl = 2; } else if (k2 < m2) m2 = k2;
            if (k3 < m1) { m2 = m1; m1 = k3; jl = 3; } else if (k3 < m2) m2 = k3;

            const unsigned kmin1 = __reduce_min_sync(FULLMASK, m1);
            const unsigned win   = __ballot_sync(FULLMASK, m1 == kmin1);
            const int wl = __ffs(win) - 1;
            const int j1 = __shfl_sync(FULLMASK, 4 * lane + jl, wl);
            const unsigned cand  = (lane == wl) ? m2 : m1;
            const unsigned kmin2 = __reduce_min_sync(FULLMASK, cand);
            const float u1 = ord2f(kmin1);
            const float u2 = ord2f(kmin2);

            const int i1 = p_sh[j1];
            v_sh[j1] = v_sh[j1] - (u2 - u1);   // broadcast read, identical write
            u_sh[i]  = u2;
            p_sh[j1] = i;
            if (i1 >= 0) freeq[tail++] = i1;   // displaced row re-queued
        }

        // ---- Dijkstra augmentation for remaining free rows ----
        float v[4];
        {
            float4 vv = *(const float4*)&v_sh[4 * lane];
            v[0] = vv.x; v[1] = vv.y; v[2] = vv.z; v[3] = vv.w;
        }

        for (int q = head; q < tail; q++) {
            const int i = freeq[q];

            float dist[4] = {__int_as_float(0x7F800000), __int_as_float(0x7F800000),
                             __int_as_float(0x7F800000), __int_as_float(0x7F800000)};
            unsigned usedm = 0;
            int   i0    = i;
            int   jprev = -1;      // -1 = virtual source
            float dist0 = 0.0f;
            int   j1;
            float distF;

            while (true) {
                const float u0 = u_sh[i0];
                const float4 c4 = *(const float4*)&C[i0 * NP + 4 * lane];
                const float cc[4] = {c4.x, c4.y, c4.z, c4.w};
                const float s = dist0 - u0;

                unsigned lkey = 0xFFFFFFFFu;
                #pragma unroll
                for (int k = 0; k < 4; k++) {
                    if (!((usedm >> k) & 1u)) {
                        float cur = s + (cc[k] - v[k]);
                        if (cur < dist[k]) { dist[k] = cur; way_sh[4 * lane + k] = jprev; }
                        unsigned key = f2ord(dist[k]);
                        lkey = lkey < key ? lkey : key;
                    }
                }
                const unsigned kmin = __reduce_min_sync(FULLMASK, lkey);
                unsigned lj = 0xFFFFFFFFu;
                #pragma unroll
                for (int k = 0; k < 4; k++) {
                    if (!((usedm >> k) & 1u) && f2ord(dist[k]) == kmin) {
                        unsigned j = (unsigned)(4 * lane + k);
                        lj = lj < j ? lj : j;
                    }
                }
                j1    = (int)__reduce_min_sync(FULLMASK, lj);
                distF = ord2f(kmin);

                const int pj = p_sh[j1];
                if (pj < 0) break;                       // free column found
                if ((j1 >> 2) == lane) usedm |= 1u << (j1 & 3);
                jprev = j1; dist0 = distF; i0 = pj;
            }

            // ---- dual updates (pre-augmentation p) ----
            #pragma unroll
            for (int k = 0; k < 4; k++) {
                if ((usedm >> k) & 1u) {
                    float d = distF - dist[k];
                    v[k] -= d;
                    int r = p_sh[4 * lane + k];
                    u_sh[r] += d;
                }
            }
            if (lane == 0) u_sh[i] += distF;
            __syncwarp();

            // ---- augment along predecessor chain ----
            if (lane == 0) {
                int j = j1;
                while (true) {
                    int r = way_sh[j];
                    p_sh[j] = (r < 0) ? i : p_sh[r];
                    if (r < 0) break;
                    j = r;
                }
            }
            __syncwarp();
        }
    }
    __syncthreads();

    // ---- loss epilogue: thread tid = pred column tid ----
    const int   gi = p_sh[tid];              // matched gt row, -1 if unmatched
    const float w  = weight[tid];
    const float pr = exist_probs[b * NP + tid];

    float bce;
    float sl1 = 0.0f;
    if (gi >= 0) {
        bce = -fmaxf(logf(pr), -100.0f) * w;
        float d0 = fabsf(px - gts[gi * 3 + 0]);
        float d1 = fabsf(py - gts[gi * 3 + 1]);
        float d2 = fabsf(pz - gts[gi * 3 + 2]);
        sl1 += (d0 < 1.0f) ? 0.5f * d0 * d0 : d0 - 0.5f;
        sl1 += (d1 < 1.0f) ? 0.5f * d1 * d1 : d1 - 0.5f;
        sl1 += (d2 < 1.0f) ? 0.5f * d2 * d2 : d2 - 0.5f;
    } else {
        bce = -fmaxf(log1pf(-pr), -100.0f) * w;
    }

    // ---- block reduce (sl1, bce) ----
    float s1 = sl1, s2 = bce;
    #pragma unroll
    for (int off = 16; off; off >>= 1) {
        s1 += __shfl_xor_sync(FULLMASK, s1, off);
        s2 += __shfl_xor_sync(FULLMASK, s2, off);
    }
    const int wid = tid >> 5;
    if ((tid & 31) == 0) { red[wid] = s1; red[4 + wid] = s2; }
    __syncthreads();

    if (tid == 0) {
        float coord = (red[0] + red[1] + red[2] + red[3]) * (1.0f / (NG * 3));
        float exist = (red[4] + red[5] + red[6] + red[7]) * (1.0f / NP);
        float cd = count_pred[b] - (float)gt_counts[b];
        g_partial[b] = coord + exist + cd * cd;
        __threadfence();
        int old = atomicAdd(&g_ready, 1);
        if (old == BATCH - 1) {                 // last block finalizes
            __threadfence();
            float s = 0.0f;
            #pragma unroll
            for (int bb = 0; bb < BATCH; bb++)
                s += ((volatile float*)g_partial)[bb];
            out[0] = s * (1.0f / BATCH);
            g_ready = 0;                        // restore for next replay
        }
    }
}

extern "C" void kernel_launch(void* const* d_in, const int* in_sizes, int n_in,
                              void* d_out, int out_size)
{
    const float* pred_coords = (const float*)d_in[0]; // [32,128,3]
    const float* exist_probs = (const float*)d_in[1]; // [32,128]
    const float* count_pred  = (const float*)d_in[2]; // [32,1]
    const float* gt_coords   = (const float*)d_in[3]; // [32,64,3]
    const int*   gt_counts   = (const int*)  d_in[4]; // [32]
    const float* weight      = (const float*)d_in[5]; // [1,128]
    float* out = (float*)d_out;

    lsa_loss_kernel<<<BATCH, 128>>>(pred_coords, exist_probs, count_pred,
                                    gt_coords, gt_counts, weight, out);
}